// round 14
// baseline (speedup 1.0000x reference)
#include <cuda_runtime.h>
#include <cstdint>

#define HH 128
#define WHX 128
#define H 256
#define W 256
#define NB 4
#define CF 64
#define KK 51
#define PADK 25
#define HP (H + 2*PADK)   // 306
#define WPP (W + 2*PADK)  // 306
#define HW (H*W)          // 65536
#define WD 512             // duplicated row width (2*W)

typedef unsigned long long ull;

__device__ __forceinline__ ull pack2(float lo, float hi) {
    ull r; asm("mov.b64 %0, {%1, %2};" : "=l"(r) : "f"(lo), "f"(hi)); return r;
}
__device__ __forceinline__ void unpack2(ull v, float& lo, float& hi) {
    asm("mov.b64 {%0, %1}, %2;" : "=f"(lo), "=f"(hi) : "l"(v));
}
__device__ __forceinline__ ull ffma2(ull a, ull b, ull c) {
    ull d; asm("fma.rn.f32x2 %0, %1, %2, %3;" : "=l"(d) : "l"(a), "l"(b), "l"(c)); return d;
}
__device__ __forceinline__ uint32_t smem_u32(const void* p) {
    return (uint32_t)__cvta_generic_to_shared(p);
}
__device__ __forceinline__ void cpa8s(uint32_t dst, const void* src, int srcsize) {
    asm volatile("cp.async.ca.shared.global [%0], [%1], 8, %2;\n"
                 :: "r"(dst), "l"(src), "r"(srcsize));
}
__device__ __forceinline__ void cpa8(uint32_t dst, const void* src) {
    asm volatile("cp.async.ca.shared.global [%0], [%1], 8;\n"
                 :: "r"(dst), "l"(src));
}
#define CP_COMMIT() asm volatile("cp.async.commit_group;\n" ::: "memory")
#define CP_WAIT0()  asm volatile("cp.async.wait_group 0;\n" ::: "memory")

// Scratch buffers (allocation-free: static device globals)
// Duplicated tensors: each pixel stored twice -> [ch][y][2W]
__device__ float g_up[(size_t)NB*CF*H*WD];
__device__ float g_t1[(size_t)4*NB*KK*H*WD];
__device__ float g_t2[(size_t)4*NB*KK*H*WD];
__device__ float g_k [(size_t)4*NB*KK*H*W];   // plain (sepconv input)
// packed weights: [k][grp(3)][ic][tap(9)][10 ocpairs] float2 (pair 9 = pad)
__device__ float2 g_wp1[(size_t)4*3*CF*90];
__device__ float2 g_wp2[(size_t)4*3*KK*90];
__device__ float2 g_wp3[(size_t)4*3*KK*90];

// ---------------------------------------------------------------------------
__global__ void pack_weights(const float* __restrict__ wgt, float2* __restrict__ wp, int CIN)
{
    int idx = blockIdx.x * blockDim.x + threadIdx.x;
    int total = 4*3*CIN*90;
    if (idx >= total) return;
    int op  = idx % 10;
    int tap = (idx / 10) % 9;
    int ic  = (idx / 90) % CIN;
    int grp = (idx / (90*CIN)) % 3;
    int k   = idx / (90*CIN*3);
    float lo = 0.f, hi = 0.f;
    if (op < 9) {
        int oc = grp*18 + 2*op;
        if (oc     < KK) lo = wgt[((size_t)(k*KK + oc    )*CIN + ic)*9 + tap];
        if (oc + 1 < KK) hi = wgt[((size_t)(k*KK + oc + 1)*CIN + ic)*9 + tap];
    }
    wp[idx] = make_float2(lo, hi);
}

// ---------------------------------------------------------------------------
// 2x bilinear upsample, align_corners=True; writes duplicated {v,v} pairs.
// ---------------------------------------------------------------------------
__global__ void upsample_kernel(const float* __restrict__ x, float* __restrict__ out)
{
    int idx = blockIdx.x * blockDim.x + threadIdx.x;
    if (idx >= NB*CF*H*W) return;
    int wo = idx & (W-1);
    int ho = (idx >> 8) & (H-1);
    int bc = idx >> 16;
    const float s = (float)(HH - 1) / (float)(H - 1);
    float py = ho * s;
    float px = wo * s;
    int y0 = (int)floorf(py); int y1 = min(y0 + 1, HH - 1);
    int x0 = (int)floorf(px); int x1 = min(x0 + 1, WHX - 1);
    float wy = py - (float)y0, wx = px - (float)x0;
    const float* p = x + (size_t)bc * HH * WHX;
    float a = p[y0*WHX + x0], b = p[y0*WHX + x1];
    float c = p[y1*WHX + x0], d = p[y1*WHX + x1];
    float top = a*(1.f-wx) + b*wx;
    float bot = c*(1.f-wx) + d*wx;
    float v = top*(1.f-wy) + bot*wy;
    *(float2*)(out + ((size_t)bc*H + ho)*WD + 2*wo) = make_float2(v, v);
}

// ---------------------------------------------------------------------------
// Direct 3x3 conv + bias + relu. Inputs are duplicated tensors ([ch][y][2W]),
// so all f32x2 multiplicand pairs are ready-made {v,v}: per row the 6 pairs
// load as 3 x LDS.128, zero pack MOVs. Weights via [ic][tap][10] quads
// (45 LDS/ic). Channel loop unrolled by 2, 8B cp.async staging (tolerates the
// +2-float stagger that 16B-aligns the value loads).
// DUP_OUT stages write duplicated output for the next conv; final stage plain.
// grid: (W/64, H/16, 4*NB*3), block 256 (tx=tid&15 -> 4 px, ty=tid>>4), occ 2
// ---------------------------------------------------------------------------
template<int CIN, bool IN_PER_K, bool DUP_OUT>
__global__ void __launch_bounds__(256, 2)
conv3x3_relu8(const float* __restrict__ in, const float2* __restrict__ wpack,
              const float* __restrict__ bias, float* __restrict__ out)
{
    const int OCP = 9;
    const int NGRP = 3;
    const int SROWD = 140;                    // 2 stagger + 136 dup floats + pad
    const int TILED = 18*SROWD;               // 2520 floats per channel tile
    const int CROW = 68;                      // 8B chunks per row (136 dup floats)
    const int NCHUNK = 18*CROW;               // 1224 chunks per tile
    const int NPAIR = (CIN + 1) / 2;
    const int WOFF = CIN*180;                 // float offset of s_in (16B aligned)

    int z   = blockIdx.z;
    int k   = z / (NB*NGRP);
    int r2  = z % (NB*NGRP);
    int b   = r2 / NGRP;
    int ocg = r2 % NGRP;
    int oc0 = ocg * 18;
    int gx0 = blockIdx.x * 64;
    int gy0 = blockIdx.y * 16;

    extern __shared__ __align__(16) float sm[];
    float2* s_w2 = (float2*)sm;        // [CIN][9][10]
    float*  s_in = sm + WOFF;          // [2 buf][2 ch][18][140]

    int tid = threadIdx.x;
    int tx = tid & 15, ty = tid >> 4;

    // stage packed weights (linear, async; rides along with first group)
    {
        const float2* wsrc = wpack + (size_t)(k*NGRP + ocg) * CIN * 90;
        uint32_t wdst = smem_u32(s_w2);
        for (int i = tid; i < CIN*90; i += 256)
            cpa8(wdst + i*8, wsrc + i);
    }

    const float* ip = in + (size_t)(IN_PER_K ? (k*NB + b) : b) * CIN * H * WD;
    uint32_t sin_base = smem_u32(s_in);

    int dc0 = 2*gx0 - 4;   // absolute dup col of chunk 0

    // stage channel pair j (tiles 2j, 2j+1) into buffer (j&1); commits group
    auto stage = [&](int j) {
        int nch = (2*j + 2 <= CIN) ? 2 : 1;
        uint32_t dstb = sin_base + (j & 1) * (2*TILED) * 4;
        for (int s = 0; s < nch; s++) {
            const float* cp = ip + (size_t)(2*j + s) * H * WD;
            uint32_t dst = dstb + s*TILED*4;
            for (int i = tid; i < NCHUNK; i += 256) {
                int rr = i / CROW, ii = i % CROW;
                int gy = gy0 - 1 + rr;
                int dc = dc0 + 2*ii;
                bool ok = ((unsigned)gy < H) && ((unsigned)dc < WD);
                cpa8s(dst + (rr*SROWD + 2 + 2*ii)*4,
                      ok ? (cp + (size_t)gy*WD + dc) : cp, ok ? 8 : 0);
            }
        }
        CP_COMMIT();
    };

    stage(0);

    ull acc[OCP][4];
    #pragma unroll
    for (int o = 0; o < OCP; o++)
        #pragma unroll
        for (int p = 0; p < 4; p++) acc[o][p] = 0ULL;

    #pragma unroll 1
    for (int j = 0; j < NPAIR; j++) {
        CP_WAIT0();
        __syncthreads();
        if (j + 1 < NPAIR) stage(j + 1);

        int nch = (2*j + 2 <= CIN) ? 2 : 1;
        const float* buf = s_in + (j & 1) * (2*TILED);

        #pragma unroll 1
        for (int s = 0; s < nch; s++) {
            const float* sb = buf + s*TILED;
            const ull* wq = (const ull*)s_w2 + (size_t)(2*j + s)*90;

            #pragma unroll
            for (int r = 0; r < 3; r++) {
                // vr[c] = {v,v} for px gx0+4tx-1+c, at smem float idx 8tx+4+2c
                const float* rowp = sb + (ty + r)*SROWD + 8*tx + 4;
                ulonglong2 q0 = *(const ulonglong2*)(rowp + 0);   // vr0, vr1
                ulonglong2 q1 = *(const ulonglong2*)(rowp + 4);   // vr2, vr3
                ulonglong2 q2 = *(const ulonglong2*)(rowp + 8);   // vr4, vr5
                ull vr[6] = { q0.x, q0.y, q1.x, q1.y, q2.x, q2.y };

                #pragma unroll
                for (int tc = 0; tc < 3; tc++) {
                    const ull* wt = wq + (r*3 + tc)*10;   // tap base, 16B aligned
                    ulonglong2 b0 = *(const ulonglong2*)(wt + 0);
                    ulonglong2 b1 = *(const ulonglong2*)(wt + 2);
                    ulonglong2 b2 = *(const ulonglong2*)(wt + 4);
                    ulonglong2 b3 = *(const ulonglong2*)(wt + 6);
                    ull w8 = wt[8];
                    ull w[9] = { b0.x, b0.y, b1.x, b1.y, b2.x, b2.y, b3.x, b3.y, w8 };
                    #pragma unroll
                    for (int op = 0; op < OCP; op++) {
                        #pragma unroll
                        for (int p = 0; p < 4; p++)
                            acc[op][p] = ffma2(w[op], vr[p + tc], acc[op][p]);
                    }
                }
            }
        }
    }

    // epilogue: bias + relu + store
    int oy = gy0 + ty, ox = gx0 + tx*4;
    #pragma unroll
    for (int opi = 0; opi < OCP; opi++) {
        float lo[4], hi[4];
        #pragma unroll
        for (int p = 0; p < 4; p++) unpack2(acc[opi][p], lo[p], hi[p]);
        int oc = oc0 + 2*opi;
        if (DUP_OUT) {
            float* outp = out + (size_t)(k*NB + b) * KK * H * WD;
            if (oc < KK) {
                float bv = bias[k*KK + oc];
                float r0 = fmaxf(lo[0] + bv, 0.f), r1 = fmaxf(lo[1] + bv, 0.f);
                float r2_ = fmaxf(lo[2] + bv, 0.f), r3 = fmaxf(lo[3] + bv, 0.f);
                float* dst = outp + ((size_t)oc*H + oy)*WD + 2*ox;
                *(float4*)(dst)     = make_float4(r0, r0, r1, r1);
                *(float4*)(dst + 4) = make_float4(r2_, r2_, r3, r3);
            }
            if (oc + 1 < KK) {
                float bv = bias[k*KK + oc + 1];
                float r0 = fmaxf(hi[0] + bv, 0.f), r1 = fmaxf(hi[1] + bv, 0.f);
                float r2_ = fmaxf(hi[2] + bv, 0.f), r3 = fmaxf(hi[3] + bv, 0.f);
                float* dst = outp + ((size_t)(oc+1)*H + oy)*WD + 2*ox;
                *(float4*)(dst)     = make_float4(r0, r0, r1, r1);
                *(float4*)(dst + 4) = make_float4(r2_, r2_, r3, r3);
            }
        } else {
            float* outp = out + (size_t)(k*NB + b) * KK * HW;
            if (oc < KK) {
                float bv = bias[k*KK + oc];
                float4 v4;
                v4.x = fmaxf(lo[0] + bv, 0.f); v4.y = fmaxf(lo[1] + bv, 0.f);
                v4.z = fmaxf(lo[2] + bv, 0.f); v4.w = fmaxf(lo[3] + bv, 0.f);
                *(float4*)(outp + (size_t)oc*HW + oy*W + ox) = v4;
            }
            if (oc + 1 < KK) {
                float bv = bias[k*KK + oc + 1];
                float4 v4;
                v4.x = fmaxf(hi[0] + bv, 0.f); v4.y = fmaxf(hi[1] + bv, 0.f);
                v4.z = fmaxf(hi[2] + bv, 0.f); v4.w = fmaxf(hi[3] + bv, 0.f);
                *(float4*)(outp + (size_t)(oc+1)*HW + oy*W + ox) = v4;
            }
        }
    }
}

// ---------------------------------------------------------------------------
// Adaptive separable conv (R5-proven): 1 output px per thread, packed f32x2
// over taps with parity phase. grid: (W/32, H/8, NB), block (32,8)
// ---------------------------------------------------------------------------
__global__ void __launch_bounds__(256)
sepconv2_kernel(const float* __restrict__ i1, const float* __restrict__ i2,
                const float* __restrict__ gk, float* __restrict__ out)
{
    const int SW = 84;
    int b   = blockIdx.z;
    int gx0 = blockIdx.x * 32;
    int gy0 = blockIdx.y * 8;
    int tx  = threadIdx.x, ty = threadIdx.y;
    int tid = ty * 32 + tx;
    int y = gy0 + ty, x = gx0 + tx;
    int q = tx & 1;
    int col0 = tx - q;

    __shared__ __align__(16) float s_img[58 * SW];

    float acc[3] = {0.f, 0.f, 0.f};

    #pragma unroll 1
    for (int im = 0; im < 2; im++) {
        const float* ip  = im ? i2 : i1;
        const float* kvp = gk + (((size_t)(im*2 + 0)*NB + b)*KK)*HW + (size_t)y*W + x;
        const float* khp = gk + (((size_t)(im*2 + 1)*NB + b)*KK)*HW + (size_t)y*W + x;

        ull KP[26];
        #pragma unroll
        for (int m = 0; m < 26; m++) {
            int t0 = 2*m - q, t1 = 2*m + 1 - q;
            float lo = ((unsigned)t0 < KK) ? khp[(size_t)t0 * HW] : 0.f;
            float hi = ((unsigned)t1 < KK) ? khp[(size_t)t1 * HW] : 0.f;
            KP[m] = pack2(lo, hi);
        }

        #pragma unroll 1
        for (int c = 0; c < 3; c++) {
            const float* cp = ip + ((size_t)b*3 + c) * HP * WPP;
            __syncthreads();
            for (int i = tid; i < 58*SW; i += 256) {
                int rr = i / SW, cc = i % SW;
                s_img[i] = (cc < 82) ? cp[(size_t)(gy0 + rr)*WPP + gx0 + cc] : 0.f;
            }
            __syncthreads();

            ull acc2 = 0ULL;
            #pragma unroll 1
            for (int i = 0; i < KK; i++) {
                const ull* rp = (const ull*)(s_img + (ty + i)*SW + col0);
                ull hs = 0ULL;
                #pragma unroll
                for (int m = 0; m < 26; m++) hs = ffma2(KP[m], rp[m], hs);
                float kv = kvp[(size_t)i * HW];
                acc2 = ffma2(pack2(kv, kv), hs, acc2);
            }
            float lo, hi; unpack2(acc2, lo, hi);
            acc[c] += lo + hi;
        }
    }

    size_t ob = ((size_t)b*3)*HW + (size_t)y*W + x;
    out[ob]        = acc[0];
    out[ob + HW]   = acc[1];
    out[ob + 2*HW] = acc[2];
}

// ---------------------------------------------------------------------------
extern "C" void kernel_launch(void* const* d_in, const int* in_sizes, int n_in,
                              void* d_out, int out_size)
{
    const float* x  = (const float*)d_in[0];
    const float* i1 = (const float*)d_in[1];
    const float* i2 = (const float*)d_in[2];
    const float* W1 = (const float*)d_in[3];
    const float* B1 = (const float*)d_in[4];
    const float* W2 = (const float*)d_in[5];
    const float* B2 = (const float*)d_in[6];
    const float* W3 = (const float*)d_in[7];
    const float* B3 = (const float*)d_in[8];
    float* out = (float*)d_out;

    float* up = nullptr; float* t1 = nullptr; float* t2 = nullptr; float* kk = nullptr;
    float2* wp1 = nullptr; float2* wp2 = nullptr; float2* wp3 = nullptr;
    cudaGetSymbolAddress((void**)&up, g_up);
    cudaGetSymbolAddress((void**)&t1, g_t1);
    cudaGetSymbolAddress((void**)&t2, g_t2);
    cudaGetSymbolAddress((void**)&kk, g_k);
    cudaGetSymbolAddress((void**)&wp1, g_wp1);
    cudaGetSymbolAddress((void**)&wp2, g_wp2);
    cudaGetSymbolAddress((void**)&wp3, g_wp3);

    size_t smem64 = (size_t)(64*180 + 4*18*140) * sizeof(float);   // 86400 B
    size_t smem51 = (size_t)(51*180 + 4*18*140) * sizeof(float);   // 77040 B
    cudaFuncSetAttribute((const void*)conv3x3_relu8<64, false, true>,
                         cudaFuncAttributeMaxDynamicSharedMemorySize, (int)smem64);
    cudaFuncSetAttribute((const void*)conv3x3_relu8<51, true, true>,
                         cudaFuncAttributeMaxDynamicSharedMemorySize, (int)smem51);
    cudaFuncSetAttribute((const void*)conv3x3_relu8<51, true, false>,
                         cudaFuncAttributeMaxDynamicSharedMemorySize, (int)smem51);

    // 0) pack weights (tiny)
    {
        int t64 = 4*3*64*90, t51 = 4*3*51*90;
        pack_weights<<<(t64 + 255)/256, 256>>>(W1, wp1, 64);
        pack_weights<<<(t51 + 255)/256, 256>>>(W2, wp2, 51);
        pack_weights<<<(t51 + 255)/256, 256>>>(W3, wp3, 51);
    }

    // 1) upsample features (duplicated output)
    {
        int n = NB*CF*H*W;
        upsample_kernel<<<(n + 255)/256, 256>>>(x, up);
    }

    // 2) three conv stages (dup in; stages 1-2 dup out, stage 3 plain out)
    dim3 cgrid(W/64, H/16, 4*NB*3);
    conv3x3_relu8<64, false, true ><<<cgrid, 256, smem64>>>(up, wp1, B1, t1);
    conv3x3_relu8<51, true,  true ><<<cgrid, 256, smem51>>>(t1, wp2, B2, t2);
    conv3x3_relu8<51, true,  false><<<cgrid, 256, smem51>>>(t2, wp3, B3, kk);

    // 3) separable filtering of both images + sum
    {
        dim3 g(W/32, H/8, NB);
        dim3 blk(32, 8);
        sepconv2_kernel<<<g, blk>>>(i1, i2, kk, out);
    }
}

// round 15
// speedup vs baseline: 1.2827x; 1.2827x over previous
#include <cuda_runtime.h>
#include <cstdint>

#define HH 128
#define WHX 128
#define H 256
#define W 256
#define NB 4
#define CF 64
#define KK 51
#define PADK 25
#define HP (H + 2*PADK)   // 306
#define WPP (W + 2*PADK)  // 306
#define WPAD 308           // padded image row stride (16B-aligned rows)
#define HW (H*W)          // 65536

typedef unsigned long long ull;

__device__ __forceinline__ ull pack2(float lo, float hi) {
    ull r; asm("mov.b64 %0, {%1, %2};" : "=l"(r) : "f"(lo), "f"(hi)); return r;
}
__device__ __forceinline__ void unpack2(ull v, float& lo, float& hi) {
    asm("mov.b64 {%0, %1}, %2;" : "=f"(lo), "=f"(hi) : "l"(v));
}
__device__ __forceinline__ ull ffma2(ull a, ull b, ull c) {
    ull d; asm("fma.rn.f32x2 %0, %1, %2, %3;" : "=l"(d) : "l"(a), "l"(b), "l"(c)); return d;
}
__device__ __forceinline__ uint32_t smem_u32(const void* p) {
    return (uint32_t)__cvta_generic_to_shared(p);
}
__device__ __forceinline__ void cpa16(uint32_t dst, const void* src, int srcsize) {
    asm volatile("cp.async.cg.shared.global [%0], [%1], 16, %2;\n"
                 :: "r"(dst), "l"(src), "r"(srcsize));
}
__device__ __forceinline__ void cpa16f(uint32_t dst, const void* src) {
    asm volatile("cp.async.cg.shared.global [%0], [%1], 16;\n"
                 :: "r"(dst), "l"(src));
}
__device__ __forceinline__ void cpa8(uint32_t dst, const void* src) {
    asm volatile("cp.async.ca.shared.global [%0], [%1], 8;\n"
                 :: "r"(dst), "l"(src));
}
#define CP_COMMIT() asm volatile("cp.async.commit_group;\n" ::: "memory")
#define CP_WAIT0()  asm volatile("cp.async.wait_group 0;\n" ::: "memory")

// Scratch buffers (allocation-free: static device globals)
__device__ float g_up[(size_t)NB*CF*H*W];
__device__ float g_t1[(size_t)4*NB*KK*H*W];
__device__ float g_t2[(size_t)4*NB*KK*H*W];
__device__ float g_k [(size_t)4*NB*KK*H*W];   // k=0:k1v 1:k1h 2:k2v 3:k2h
// padded images: [im(2)][b][c][306][308]
__device__ float g_imp[(size_t)2*NB*3*HP*WPAD];
// packed weights: [k][grp(3)][ic][tap(9)][10 ocpairs] float2 (pair 9 = pad)
__device__ float2 g_wp1[(size_t)4*3*CF*90];
__device__ float2 g_wp2[(size_t)4*3*KK*90];
__device__ float2 g_wp3[(size_t)4*3*KK*90];

// ---------------------------------------------------------------------------
__global__ void pack_weights(const float* __restrict__ wgt, float2* __restrict__ wp, int CIN)
{
    int idx = blockIdx.x * blockDim.x + threadIdx.x;
    int total = 4*3*CIN*90;
    if (idx >= total) return;
    int op  = idx % 10;
    int tap = (idx / 10) % 9;
    int ic  = (idx / 90) % CIN;
    int grp = (idx / (90*CIN)) % 3;
    int k   = idx / (90*CIN*3);
    float lo = 0.f, hi = 0.f;
    if (op < 9) {
        int oc = grp*18 + 2*op;
        if (oc     < KK) lo = wgt[((size_t)(k*KK + oc    )*CIN + ic)*9 + tap];
        if (oc + 1 < KK) hi = wgt[((size_t)(k*KK + oc + 1)*CIN + ic)*9 + tap];
    }
    wp[idx] = make_float2(lo, hi);
}

// ---------------------------------------------------------------------------
// Repack i1/i2 into 16B-aligned stride-308 rows: [im][b][c][306][308]
// ---------------------------------------------------------------------------
__global__ void pad_images(const float* __restrict__ i1, const float* __restrict__ i2,
                           float* __restrict__ dst)
{
    int idx = blockIdx.x * blockDim.x + threadIdx.x;
    const int PER = 153 * HP;               // float2 per channel image
    if (idx >= 2*NB*3*PER) return;
    int col2 = idx % 153;
    int row  = (idx / 153) % HP;
    int ch   = idx / PER;                   // im*12 + b*3 + c
    int im   = ch / (NB*3);
    int lc   = ch % (NB*3);
    const float* src = (im ? i2 : i1);
    float2 v = *(const float2*)(src + ((size_t)lc*HP + row)*WPP + 2*col2);
    *(float2*)(dst + ((size_t)ch*HP + row)*WPAD + 2*col2) = v;
}

// ---------------------------------------------------------------------------
// 2x bilinear upsample, align_corners=True; 2 px per thread (shared y-interp)
// ---------------------------------------------------------------------------
__global__ void upsample_kernel2(const float* __restrict__ x, float* __restrict__ out)
{
    int idx = blockIdx.x * blockDim.x + threadIdx.x;
    if (idx >= NB*CF*H*(W/2)) return;
    int wp = idx & 127;
    int ho = (idx >> 7) & (H-1);
    int bc = idx >> 15;
    const float s = (float)(HH - 1) / (float)(H - 1);
    float py = ho * s;
    int y0 = (int)floorf(py); int y1 = min(y0 + 1, HH - 1);
    float wy = py - (float)y0;
    const float* p = x + (size_t)bc * HH * WHX;
    float r[2];
    #pragma unroll
    for (int kk = 0; kk < 2; kk++) {
        int wo = 2*wp + kk;
        float px = wo * s;
        int x0 = (int)floorf(px); int x1 = min(x0 + 1, WHX - 1);
        float wx = px - (float)x0;
        float a = p[y0*WHX + x0], b = p[y0*WHX + x1];
        float c = p[y1*WHX + x0], d = p[y1*WHX + x1];
        float top = a*(1.f-wx) + b*wx;
        float bot = c*(1.f-wx) + d*wx;
        r[kk] = top*(1.f-wy) + bot*wy;
    }
    *(float2*)(out + ((size_t)bc*H + ho)*W + 2*wp) = make_float2(r[0], r[1]);
}

// ---------------------------------------------------------------------------
// Direct 3x3 conv + bias + relu (R12-proven, UNCHANGED). Packed f32x2 over oc
// pairs, cp.async staging, channel loop unrolled by 2, weight quads via
// LDS.128 from the [ic][tap][10] layout (45 loads/ic).
// grid: (W/64, H/16, 4*NB*3), block 256 (tx=tid&15 -> 4 px, ty=tid>>4)
// ---------------------------------------------------------------------------
template<int CIN, bool IN_PER_K>
__global__ void __launch_bounds__(256, 2)
conv3x3_relu6(const float* __restrict__ in, const float2* __restrict__ wpack,
              const float* __restrict__ bias, float* __restrict__ out)
{
    const int OCP = 9;
    const int NGRP = 3;
    const int SROW = 72;
    const int TILE = 18*SROW;                 // one channel tile (1296 floats)
    const int NCHUNK = 18*18;                 // 16B chunks per tile
    const int NPAIR = (CIN + 1) / 2;
    const int WOFF = CIN*180;                 // float offset of s_in (16B aligned)

    int z   = blockIdx.z;
    int k   = z / (NB*NGRP);
    int r2  = z % (NB*NGRP);
    int b   = r2 / NGRP;
    int ocg = r2 % NGRP;
    int oc0 = ocg * 18;
    int gx0 = blockIdx.x * 64;
    int gy0 = blockIdx.y * 16;

    extern __shared__ __align__(16) float sm[];
    float2* s_w2 = (float2*)sm;        // [CIN][9][10]
    float*  s_in = sm + WOFF;          // [2 buf][2 ch][18][72]

    int tid = threadIdx.x;
    int tx = tid & 15, ty = tid >> 4;

    // stage packed weights (linear, async; rides along with first group)
    {
        const float2* wsrc = wpack + (size_t)(k*NGRP + ocg) * CIN * 90;
        uint32_t wdst = smem_u32(s_w2);
        for (int i = tid; i < CIN*90; i += 256)
            cpa8(wdst + i*8, wsrc + i);
    }

    const float* ip = in + (size_t)(IN_PER_K ? (k*NB + b) : b) * CIN * HW;
    uint32_t sin_base = smem_u32(s_in);

    // stage channel pair j (tiles 2j, 2j+1) into buffer (j&1); commits group
    auto stage = [&](int j) {
        int nch = (2*j + 2 <= CIN) ? 2 : 1;
        uint32_t dstb = sin_base + (j & 1) * (2*TILE) * 4;
        for (int s = 0; s < nch; s++) {
            const float* cp = ip + (size_t)(2*j + s) * HW;
            uint32_t dst = dstb + s*TILE*4;
            for (int i = tid; i < NCHUNK; i += 256) {
                int rr = i / 18, f = i % 18;
                int gy = gy0 - 1 + rr;
                int gx = gx0 - 4 + 4*f;
                bool ok = ((unsigned)gy < H) && (gx >= 0) && (gx < W);
                cpa16(dst + (rr*SROW + f*4)*4, ok ? (cp + gy*W + gx) : cp, ok ? 16 : 0);
            }
        }
        CP_COMMIT();
    };

    stage(0);

    ull acc[OCP][4];
    #pragma unroll
    for (int o = 0; o < OCP; o++)
        #pragma unroll
        for (int p = 0; p < 4; p++) acc[o][p] = 0ULL;

    #pragma unroll 1
    for (int j = 0; j < NPAIR; j++) {
        CP_WAIT0();
        __syncthreads();
        if (j + 1 < NPAIR) stage(j + 1);

        int nch = (2*j + 2 <= CIN) ? 2 : 1;
        const float* buf = s_in + (j & 1) * (2*TILE);

        #pragma unroll 1
        for (int s = 0; s < nch; s++) {
            const float* sb = buf + s*TILE;
            const ull* wq = (const ull*)s_w2 + (size_t)(2*j + s)*90;

            #pragma unroll
            for (int r = 0; r < 3; r++) {
                const float* rowp = sb + (ty + r)*SROW + tx*4 + 3;
                float e0 = rowp[0];
                float4 m4 = *(const float4*)(rowp + 1);   // 16B-aligned
                float e5 = rowp[5];
                ull vr[6];
                vr[0] = pack2(e0,   e0);
                vr[1] = pack2(m4.x, m4.x);
                vr[2] = pack2(m4.y, m4.y);
                vr[3] = pack2(m4.z, m4.z);
                vr[4] = pack2(m4.w, m4.w);
                vr[5] = pack2(e5,   e5);

                #pragma unroll
                for (int tc = 0; tc < 3; tc++) {
                    const ull* wt = wq + (r*3 + tc)*10;   // tap base, 16B aligned
                    ulonglong2 b0 = *(const ulonglong2*)(wt + 0);
                    ulonglong2 b1 = *(const ulonglong2*)(wt + 2);
                    ulonglong2 b2 = *(const ulonglong2*)(wt + 4);
                    ulonglong2 b3 = *(const ulonglong2*)(wt + 6);
                    ull w8 = wt[8];
                    ull w[9] = { b0.x, b0.y, b1.x, b1.y, b2.x, b2.y, b3.x, b3.y, w8 };
                    #pragma unroll
                    for (int op = 0; op < OCP; op++) {
                        #pragma unroll
                        for (int p = 0; p < 4; p++)
                            acc[op][p] = ffma2(w[op], vr[p + tc], acc[op][p]);
                    }
                }
            }
        }
    }

    // epilogue: bias + relu + store
    float* outp = out + (size_t)(k*NB + b) * KK * HW;
    int oy = gy0 + ty, ox = gx0 + tx*4;
    #pragma unroll
    for (int opi = 0; opi < OCP; opi++) {
        float lo[4], hi[4];
        #pragma unroll
        for (int p = 0; p < 4; p++) unpack2(acc[opi][p], lo[p], hi[p]);
        int oc = oc0 + 2*opi;
        if (oc < KK) {
            float bv = bias[k*KK + oc];
            float4 v4;
            v4.x = fmaxf(lo[0] + bv, 0.f); v4.y = fmaxf(lo[1] + bv, 0.f);
            v4.z = fmaxf(lo[2] + bv, 0.f); v4.w = fmaxf(lo[3] + bv, 0.f);
            *(float4*)(outp + (size_t)oc*HW + oy*W + ox) = v4;
        }
        if (oc + 1 < KK) {
            float bv = bias[k*KK + oc + 1];
            float4 v4;
            v4.x = fmaxf(hi[0] + bv, 0.f); v4.y = fmaxf(hi[1] + bv, 0.f);
            v4.z = fmaxf(hi[2] + bv, 0.f); v4.w = fmaxf(hi[3] + bv, 0.f);
            *(float4*)(outp + (size_t)(oc+1)*HW + oy*W + ox) = v4;
        }
    }
}

// ---------------------------------------------------------------------------
// Adaptive separable conv with cp.async double-buffered image tiles.
// Reads the padded stride-308 images so every tile row stages as 21 aligned
// 16B chunks. 6 tiles (im,c) pipelined: stage(t+1) overlaps compute(t).
// Packed f32x2 over taps with parity phase (R5-proven inner loop).
// grid: (W/32, H/8, NB), block (32, 8)
// ---------------------------------------------------------------------------
__global__ void __launch_bounds__(256)
sepconv4_kernel(const float* __restrict__ imp,
                const float* __restrict__ gk, float* __restrict__ out)
{
    const int SW = 84;
    const int TSZ = 58 * SW;                 // 4872 floats per tile
    int b   = blockIdx.z;
    int gx0 = blockIdx.x * 32;
    int gy0 = blockIdx.y * 8;
    int tx  = threadIdx.x, ty = threadIdx.y;
    int tid = ty * 32 + tx;
    int y = gy0 + ty, x = gx0 + tx;
    int q = tx & 1;
    int col0 = tx - q;

    __shared__ __align__(16) float s_img[2 * TSZ];
    uint32_t sbase = smem_u32(s_img);

    // stage tile t=(im,c) into buffer buf: 58 rows x 21 aligned 16B chunks
    auto stage = [&](int t, int buf) {
        int im = t / 3, c = t % 3;
        const float* cp = imp + (size_t)((im*NB + b)*3 + c) * HP * WPAD;
        uint32_t dst = sbase + buf * TSZ * 4;
        for (int i = tid; i < 58*21; i += 256) {
            int rr = i / 21, f = i % 21;
            cpa16f(dst + (rr*SW + 4*f)*4,
                   cp + (size_t)(gy0 + rr)*WPAD + gx0 + 4*f);
        }
        CP_COMMIT();
    };

    stage(0, 0);

    float acc[3] = {0.f, 0.f, 0.f};
    ull KP[26];

    #pragma unroll 1
    for (int t = 0; t < 6; t++) {
        int im = t / 3, c = t % 3;

        if (c == 0) {
            const float* khp = gk + (((size_t)(im*2 + 1)*NB + b)*KK)*HW + (size_t)y*W + x;
            #pragma unroll
            for (int m = 0; m < 26; m++) {
                int t0 = 2*m - q, t1 = 2*m + 1 - q;
                float lo = ((unsigned)t0 < KK) ? khp[(size_t)t0 * HW] : 0.f;
                float hi = ((unsigned)t1 < KK) ? khp[(size_t)t1 * HW] : 0.f;
                KP[m] = pack2(lo, hi);
            }
        }

        CP_WAIT0();
        __syncthreads();
        if (t < 5) stage(t + 1, (t + 1) & 1);

        const float* kvp = gk + (((size_t)(im*2 + 0)*NB + b)*KK)*HW + (size_t)y*W + x;
        const float* sb = s_img + (t & 1) * TSZ;

        ull acc2 = 0ULL;
        #pragma unroll 1
        for (int i = 0; i < KK; i++) {
            const ull* rp = (const ull*)(sb + (ty + i)*SW + col0);
            ull hs = 0ULL;
            #pragma unroll
            for (int m = 0; m < 26; m++) hs = ffma2(KP[m], rp[m], hs);
            float kv = kvp[(size_t)i * HW];
            acc2 = ffma2(pack2(kv, kv), hs, acc2);
        }
        float lo, hi; unpack2(acc2, lo, hi);
        acc[c] += lo + hi;

        __syncthreads();   // all warps done reading buf (t&1) before t+2 overwrites it
    }

    size_t ob = ((size_t)b*3)*HW + (size_t)y*W + x;
    out[ob]        = acc[0];
    out[ob + HW]   = acc[1];
    out[ob + 2*HW] = acc[2];
}

// ---------------------------------------------------------------------------
extern "C" void kernel_launch(void* const* d_in, const int* in_sizes, int n_in,
                              void* d_out, int out_size)
{
    const float* x  = (const float*)d_in[0];
    const float* i1 = (const float*)d_in[1];
    const float* i2 = (const float*)d_in[2];
    const float* W1 = (const float*)d_in[3];
    const float* B1 = (const float*)d_in[4];
    const float* W2 = (const float*)d_in[5];
    const float* B2 = (const float*)d_in[6];
    const float* W3 = (const float*)d_in[7];
    const float* B3 = (const float*)d_in[8];
    float* out = (float*)d_out;

    float* up = nullptr; float* t1 = nullptr; float* t2 = nullptr; float* kk = nullptr;
    float* imp = nullptr;
    float2* wp1 = nullptr; float2* wp2 = nullptr; float2* wp3 = nullptr;
    cudaGetSymbolAddress((void**)&up, g_up);
    cudaGetSymbolAddress((void**)&t1, g_t1);
    cudaGetSymbolAddress((void**)&t2, g_t2);
    cudaGetSymbolAddress((void**)&kk, g_k);
    cudaGetSymbolAddress((void**)&imp, g_imp);
    cudaGetSymbolAddress((void**)&wp1, g_wp1);
    cudaGetSymbolAddress((void**)&wp2, g_wp2);
    cudaGetSymbolAddress((void**)&wp3, g_wp3);

    size_t smem64 = (size_t)(64*180 + 4*18*72) * sizeof(float);
    size_t smem51 = (size_t)(51*180 + 4*18*72) * sizeof(float);
    cudaFuncSetAttribute(conv3x3_relu6<64, false>,
                         cudaFuncAttributeMaxDynamicSharedMemorySize, (int)smem64);
    cudaFuncSetAttribute(conv3x3_relu6<51, true>,
                         cudaFuncAttributeMaxDynamicSharedMemorySize, (int)smem51);

    // 0) pack weights + pad images (tiny, independent of conv chain)
    {
        int t64 = 4*3*64*90, t51 = 4*3*51*90;
        pack_weights<<<(t64 + 255)/256, 256>>>(W1, wp1, 64);
        pack_weights<<<(t51 + 255)/256, 256>>>(W2, wp2, 51);
        pack_weights<<<(t51 + 255)/256, 256>>>(W3, wp3, 51);
        int np = 2*NB*3*HP*153;
        pad_images<<<(np + 255)/256, 256>>>(i1, i2, imp);
    }

    // 1) upsample features (2 px/thread)
    {
        int n = NB*CF*H*(W/2);
        upsample_kernel2<<<(n + 255)/256, 256>>>(x, up);
    }

    // 2) three conv stages (R12-proven)
    dim3 cgrid(W/64, H/16, 4*NB*3);
    conv3x3_relu6<64, false><<<cgrid, 256, smem64>>>(up, wp1, B1, t1);
    conv3x3_relu6<51, true ><<<cgrid, 256, smem51>>>(t1, wp2, B2, t2);
    conv3x3_relu6<51, true ><<<cgrid, 256, smem51>>>(t2, wp3, B3, kk);

    // 3) separable filtering of both images + sum (pipelined tiles)
    {
        dim3 g(W/32, H/8, NB);
        dim3 blk(32, 8);
        sepconv4_kernel<<<g, blk>>>(imp, kk, out);
    }
}